// round 14
// baseline (speedup 1.0000x reference)
#include <cuda_runtime.h>
#include <math.h>

#define BB   2
#define SS   2048
#define EE   2048
#define HH   16
#define KVH  4
#define DD   128
#define MM   (BB*SS)            // 4096
#define NQKV 3072
#define ATTN_SCALE 0.08838834764831845f   // 1/sqrt(128)

// ---------------- scratch (static device globals: allowed) ----------------
__device__ float g_q [(size_t)BB*HH *SS*DD];   // [B,H, S,D]  33.5 MB
__device__ float g_k [(size_t)BB*KVH*SS*DD];   // [B,KV,S,D]   8.4 MB
__device__ float g_v [(size_t)BB*KVH*SS*DD];   // [B,KV,S,D]   8.4 MB
__device__ float g_ao[(size_t)MM*EE];          // [B*S, H*D]  33.5 MB

// ============================================================================
// Kernel 1: fused QKV projection + bias + RoPE.
// C[m,n] = sum_k x[m,k]*W[n,k] + b[n]   for n in [0,3072)
//   n <  2048          -> Q (rope), head h = n>>7
//   2048 <= n < 2560   -> K (rope), kv head = (n-2048)>>7
//   n >= 2560          -> V (no rope)
// 128x128x16 SGEMM tile, 256 threads, 8x8 per-thread fragment. The N-tile is
// head-aligned, so fragment column groups (4tx+j) and (64+4tx+j) are exactly
// the RoPE pair (d, d+64) with d < 64.
// ============================================================================
__global__ __launch_bounds__(256) void qkv_kernel(
    const float* __restrict__ x,
    const float* __restrict__ Wq, const float* __restrict__ bq,
    const float* __restrict__ Wk, const float* __restrict__ bk,
    const float* __restrict__ Wv, const float* __restrict__ bv)
{
    __shared__ float As[16][132];
    __shared__ float Bs[16][132];

    const int tid = threadIdx.x;
    const int tx  = tid & 15;
    const int ty  = tid >> 4;
    const int m0  = blockIdx.y * 128;
    const int n0  = blockIdx.x * 128;

    const int lrow = tid >> 2;          // 0..63
    const int kq   = (tid & 3) << 2;    // 0,4,8,12

    // region selection (uniform per CTA: N-tile never crosses a region)
    int nbase; const float* W; const float* bvec;
    if (n0 < 2048)      { nbase = 0;    W = Wq; bvec = bq; }
    else if (n0 < 2560) { nbase = 2048; W = Wk; bvec = bk; }
    else                { nbase = 2560; W = Wv; bvec = bv; }

    const float* ap0 = x + (size_t)(m0 + lrow) * EE + kq;
    const float* ap1 = ap0 + (size_t)64 * EE;
    const float* bp0 = W + (size_t)(n0 - nbase + lrow) * EE + kq;
    const float* bp1 = bp0 + (size_t)64 * EE;

    float acc[8][8];
#pragma unroll
    for (int i = 0; i < 8; i++)
#pragma unroll
        for (int j = 0; j < 8; j++) acc[i][j] = 0.f;

    for (int k0 = 0; k0 < EE; k0 += 16) {
        float4 a0 = *(const float4*)(ap0 + k0);
        float4 a1 = *(const float4*)(ap1 + k0);
        float4 b0 = *(const float4*)(bp0 + k0);
        float4 b1 = *(const float4*)(bp1 + k0);
        __syncthreads();
        As[kq+0][lrow]    = a0.x; As[kq+1][lrow]    = a0.y;
        As[kq+2][lrow]    = a0.z; As[kq+3][lrow]    = a0.w;
        As[kq+0][lrow+64] = a1.x; As[kq+1][lrow+64] = a1.y;
        As[kq+2][lrow+64] = a1.z; As[kq+3][lrow+64] = a1.w;
        Bs[kq+0][lrow]    = b0.x; Bs[kq+1][lrow]    = b0.y;
        Bs[kq+2][lrow]    = b0.z; Bs[kq+3][lrow]    = b0.w;
        Bs[kq+0][lrow+64] = b1.x; Bs[kq+1][lrow+64] = b1.y;
        Bs[kq+2][lrow+64] = b1.z; Bs[kq+3][lrow+64] = b1.w;
        __syncthreads();
#pragma unroll
        for (int kk = 0; kk < 16; kk++) {
            float4 A0 = *(const float4*)&As[kk][4*ty];
            float4 A1 = *(const float4*)&As[kk][64 + 4*ty];
            float4 B0 = *(const float4*)&Bs[kk][4*tx];
            float4 B1 = *(const float4*)&Bs[kk][64 + 4*tx];
            float ar[8] = {A0.x,A0.y,A0.z,A0.w,A1.x,A1.y,A1.z,A1.w};
            float br[8] = {B0.x,B0.y,B0.z,B0.w,B1.x,B1.y,B1.z,B1.w};
#pragma unroll
            for (int i = 0; i < 8; i++)
#pragma unroll
                for (int j = 0; j < 8; j++)
                    acc[i][j] = fmaf(ar[i], br[j], acc[i][j]);
        }
    }

    // ---------------- epilogue: bias + RoPE + scatter ----------------
    const int bi  = m0 >> 11;              // batch (m tile never crosses batch)
    const int si0 = (m0 & (SS - 1)) + 4*ty;

    float bias0[4], bias1[4];
#pragma unroll
    for (int j = 0; j < 4; j++) {
        bias0[j] = bvec[n0 - nbase + 4*tx + j];
        bias1[j] = bvec[n0 - nbase + 64 + 4*tx + j];
    }

    float* dst; bool rope;
    if (n0 < 2048) {
        int h = n0 >> 7;
        dst = g_q + (((size_t)bi*HH + h) * SS) * DD;  rope = true;
    } else if (n0 < 2560) {
        int kv = (n0 - 2048) >> 7;
        dst = g_k + (((size_t)bi*KVH + kv) * SS) * DD; rope = true;
    } else {
        int kv = (n0 - 2560) >> 7;
        dst = g_v + (((size_t)bi*KVH + kv) * SS) * DD; rope = false;
    }

    float invf[4];
#pragma unroll
    for (int j = 0; j < 4; j++)
        invf[j] = powf(10000.0f, -(float)(4*tx + j) * (1.0f / 64.0f));

#pragma unroll
    for (int i = 0; i < 8; i++) {
        int s = si0 + ((i < 4) ? i : (60 + i));   // rows 4ty+i and 64+4ty+(i-4)
        float out0[4], out1[4];
#pragma unroll
        for (int j = 0; j < 4; j++) {
            float v0 = acc[i][j]     + bias0[j];
            float v1 = acc[i][4 + j] + bias1[j];
            if (rope) {
                float sn, cs;
                sincosf((float)s * invf[j], &sn, &cs);
                out0[j] = v0 * cs - v1 * sn;
                out1[j] = v1 * cs + v0 * sn;
            } else {
                out0[j] = v0;
                out1[j] = v1;
            }
        }
        float* row = dst + (size_t)s * DD;
        *(float4*)(row + 4*tx)      = make_float4(out0[0], out0[1], out0[2], out0[3]);
        *(float4*)(row + 64 + 4*tx) = make_float4(out1[0], out1[1], out1[2], out1[3]);
    }
}

// ============================================================================
// Kernel 2: causal flash attention, fp32, 64x64 tiles, online softmax.
// grid = (32 q-tiles [reversed: biggest first], 32 = B*H); 256 threads.
// Fragment mapping: thread(ty,tx) owns score rows {ty+16w}, cols {tx+16u};
// O rows {ty+16w}, cols {4tx+j, 64+4tx+j}. Row statistics reduce across the
// 16 lanes sharing ty via shfl.xor (width-16 groups inside each warp).
// ============================================================================
#define ATT_SMEM ((3*64*132 + 64*68) * 4)   // 118784 B

__global__ __launch_bounds__(256) void attn_kernel()
{
    extern __shared__ float sm[];
    float* Qs = sm;                    // [64][132]  (row m, d)
    float* Ks = sm + 64*132;           // [64][132]  (row n, d)
    float* Vs = sm + 2*64*132;         // [64][132]  (row n, d)
    float* Ps = sm + 3*64*132;         // [64][68]   (row m, n)

    const int tid = threadIdx.x;
    const int tx  = tid & 15;
    const int ty  = tid >> 4;
    const int qt  = (int)(gridDim.x - 1) - (int)blockIdx.x;  // big tiles first
    const int bh  = blockIdx.y;
    const int b   = bh >> 4;
    const int h   = bh & 15;
    const int kvh = h >> 2;            // G = 4
    const int q0  = qt * 64;

    const float* qbase = g_q + (((size_t)b*HH  + h  ) * SS + q0) * DD;
    const float* kbase = g_k + (((size_t)b*KVH + kvh) * SS) * DD;
    const float* vbase = g_v + (((size_t)b*KVH + kvh) * SS) * DD;

    // load Q tile once
#pragma unroll
    for (int i = 0; i < 8; i++) {
        int f  = tid + 256*i;
        int r  = f >> 5;
        int d4 = (f & 31) << 2;
        *(float4*)&Qs[r*132 + d4] = *(const float4*)(qbase + (size_t)r*DD + d4);
    }

    float o[4][8];
    float mi[4], li[4];
#pragma unroll
    for (int w = 0; w < 4; w++) {
        mi[w] = -1e30f; li[w] = 0.f;
#pragma unroll
        for (int j = 0; j < 8; j++) o[w][j] = 0.f;
    }

    const int nk = qt + 1;
    for (int kt = 0; kt < nk; kt++) {
        const float* kp = kbase + (size_t)kt * 64 * DD;
        const float* vp = vbase + (size_t)kt * 64 * DD;

        __syncthreads();   // previous iteration finished reading Ks/Vs/Ps
#pragma unroll
        for (int i = 0; i < 8; i++) {
            int f  = tid + 256*i;
            int r  = f >> 5;
            int d4 = (f & 31) << 2;
            *(float4*)&Ks[r*132 + d4] = *(const float4*)(kp + (size_t)r*DD + d4);
            *(float4*)&Vs[r*132 + d4] = *(const float4*)(vp + (size_t)r*DD + d4);
        }
        __syncthreads();

        // ---- scores S = Q K^T ----
        float sc[4][4];
#pragma unroll
        for (int w = 0; w < 4; w++)
#pragma unroll
            for (int u = 0; u < 4; u++) sc[w][u] = 0.f;

#pragma unroll 4
        for (int k = 0; k < DD; k += 4) {
            float4 qv[4], kv[4];
#pragma unroll
            for (int w = 0; w < 4; w++) qv[w] = *(const float4*)&Qs[(ty + 16*w)*132 + k];
#pragma unroll
            for (int u = 0; u < 4; u++) kv[u] = *(const float4*)&Ks[(tx + 16*u)*132 + k];
#pragma unroll
            for (int w = 0; w < 4; w++)
#pragma unroll
                for (int u = 0; u < 4; u++) {
                    sc[w][u] = fmaf(qv[w].x, kv[u].x, sc[w][u]);
                    sc[w][u] = fmaf(qv[w].y, kv[u].y, sc[w][u]);
                    sc[w][u] = fmaf(qv[w].z, kv[u].z, sc[w][u]);
                    sc[w][u] = fmaf(qv[w].w, kv[u].w, sc[w][u]);
                }
        }

        // ---- scale, causal mask, online softmax ----
        const bool diag = (kt == qt);
        float alpha[4];
#pragma unroll
        for (int w = 0; w < 4; w++) {
            const int r = ty + 16*w;
            float rowm = -1e30f;
#pragma unroll
            for (int u = 0; u < 4; u++) {
                float s = sc[w][u] * ATTN_SCALE;
                if (diag && (tx + 16*u > r)) s = -1e30f;
                sc[w][u] = s;
                rowm = fmaxf(rowm, s);
            }
#pragma unroll
            for (int off = 8; off >= 1; off >>= 1)
                rowm = fmaxf(rowm, __shfl_xor_sync(0xffffffffu, rowm, off));
            float mnew = fmaxf(mi[w], rowm);
            alpha[w] = __expf(mi[w] - mnew);
            float rs = 0.f;
#pragma unroll
            for (int u = 0; u < 4; u++) {
                float p = __expf(sc[w][u] - mnew);
                Ps[r*68 + tx + 16*u] = p;
                rs += p;
            }
#pragma unroll
            for (int off = 8; off >= 1; off >>= 1)
                rs += __shfl_xor_sync(0xffffffffu, rs, off);
            li[w] = li[w] * alpha[w] + rs;
            mi[w] = mnew;
        }
        __syncthreads();   // Ps visible to all

        // ---- rescale O and accumulate O += P V ----
#pragma unroll
        for (int w = 0; w < 4; w++)
#pragma unroll
            for (int j = 0; j < 8; j++) o[w][j] *= alpha[w];

#pragma unroll 4
        for (int n = 0; n < 64; n += 4) {
            float pr[4][4];
#pragma unroll
            for (int w = 0; w < 4; w++) {
                float4 t = *(const float4*)&Ps[(ty + 16*w)*68 + n];
                pr[w][0] = t.x; pr[w][1] = t.y; pr[w][2] = t.z; pr[w][3] = t.w;
            }
#pragma unroll
            for (int nn = 0; nn < 4; nn++) {
                float4 v0 = *(const float4*)&Vs[(n + nn)*132 + 4*tx];
                float4 v1 = *(const float4*)&Vs[(n + nn)*132 + 64 + 4*tx];
#pragma unroll
                for (int w = 0; w < 4; w++) {
                    float p = pr[w][nn];
                    o[w][0] = fmaf(p, v0.x, o[w][0]);
                    o[w][1] = fmaf(p, v0.y, o[w][1]);
                    o[w][2] = fmaf(p, v0.z, o[w][2]);
                    o[w][3] = fmaf(p, v0.w, o[w][3]);
                    o[w][4] = fmaf(p, v1.x, o[w][4]);
                    o[w][5] = fmaf(p, v1.y, o[w][5]);
                    o[w][6] = fmaf(p, v1.z, o[w][6]);
                    o[w][7] = fmaf(p, v1.w, o[w][7]);
                }
            }
        }
    }

    // ---- normalize and write to g_ao [B*S, H*D] ----
#pragma unroll
    for (int w = 0; w < 4; w++) {
        const int r = ty + 16*w;
        const int s = q0 + r;
        const float inv = 1.0f / li[w];
        float* dst = g_ao + ((size_t)b*SS + s) * EE + h*DD + 4*tx;
        *(float4*)dst =
            make_float4(o[w][0]*inv, o[w][1]*inv, o[w][2]*inv, o[w][3]*inv);
        *(float4*)(dst + 64) =
            make_float4(o[w][4]*inv, o[w][5]*inv, o[w][6]*inv, o[w][7]*inv);
    }
}

// ============================================================================
// Kernel 3: output projection. out[m,e] = sum_hd ao[m,hd] * Wo[e,hd]
// Same 128x128x16 SGEMM skeleton, no bias, direct to d_out.
// ============================================================================
__global__ __launch_bounds__(256) void oproj_kernel(
    const float* __restrict__ Wo, float* __restrict__ out)
{
    __shared__ float As[16][132];
    __shared__ float Bs[16][132];

    const int tid = threadIdx.x;
    const int tx  = tid & 15;
    const int ty  = tid >> 4;
    const int m0  = blockIdx.y * 128;
    const int n0  = blockIdx.x * 128;

    const int lrow = tid >> 2;
    const int kq   = (tid & 3) << 2;

    const float* ap0 = g_ao + (size_t)(m0 + lrow) * EE + kq;
    const float* ap1 = ap0 + (size_t)64 * EE;
    const float* bp0 = Wo + (size_t)(n0 + lrow) * EE + kq;
    const float* bp1 = bp0 + (size_t)64 * EE;

    float acc[8][8];
#pragma unroll
    for (int i = 0; i < 8; i++)
#pragma unroll
        for (int j = 0; j < 8; j++) acc[i][j] = 0.f;

    for (int k0 = 0; k0 < EE; k0 += 16) {
        float4 a0 = *(const float4*)(ap0 + k0);
        float4 a1 = *(const float4*)(ap1 + k0);
        float4 b0 = *(const float4*)(bp0 + k0);
        float4 b1 = *(const float4*)(bp1 + k0);
        __syncthreads();
        As[kq+0][lrow]    = a0.x; As[kq+1][lrow]    = a0.y;
        As[kq+2][lrow]    = a0.z; As[kq+3][lrow]    = a0.w;
        As[kq+0][lrow+64] = a1.x; As[kq+1][lrow+64] = a1.y;
        As[kq+2][lrow+64] = a1.z; As[kq+3][lrow+64] = a1.w;
        Bs[kq+0][lrow]    = b0.x; Bs[kq+1][lrow]    = b0.y;
        Bs[kq+2][lrow]    = b0.z; Bs[kq+3][lrow]    = b0.w;
        Bs[kq+0][lrow+64] = b1.x; Bs[kq+1][lrow+64] = b1.y;
        Bs[kq+2][lrow+64] = b1.z; Bs[kq+3][lrow+64] = b1.w;
        __syncthreads();
#pragma unroll
        for (int kk = 0; kk < 16; kk++) {
            float4 A0 = *(const float4*)&As[kk][4*ty];
            float4 A1 = *(const float4*)&As[kk][64 + 4*ty];
            float4 B0 = *(const float4*)&Bs[kk][4*tx];
            float4 B1 = *(const float4*)&Bs[kk][64 + 4*tx];
            float ar[8] = {A0.x,A0.y,A0.z,A0.w,A1.x,A1.y,A1.z,A1.w};
            float br[8] = {B0.x,B0.y,B0.z,B0.w,B1.x,B1.y,B1.z,B1.w};
#pragma unroll
            for (int i = 0; i < 8; i++)
#pragma unroll
                for (int j = 0; j < 8; j++)
                    acc[i][j] = fmaf(ar[i], br[j], acc[i][j]);
        }
    }

#pragma unroll
    for (int i = 0; i < 8; i++) {
        int m = m0 + 4*ty + ((i < 4) ? i : (60 + i));
        float* row = out + (size_t)m * EE + n0;
        *(float4*)(row + 4*tx) =
            make_float4(acc[i][0], acc[i][1], acc[i][2], acc[i][3]);
        *(float4*)(row + 64 + 4*tx) =
            make_float4(acc[i][4], acc[i][5], acc[i][6], acc[i][7]);
    }
}

// ============================================================================
extern "C" void kernel_launch(void* const* d_in, const int* in_sizes, int n_in,
                              void* d_out, int out_size)
{
    (void)in_sizes; (void)n_in; (void)out_size;
    const float* x  = (const float*)d_in[0];
    const float* Wq = (const float*)d_in[1];
    const float* bq = (const float*)d_in[2];
    const float* Wk = (const float*)d_in[3];
    const float* bk = (const float*)d_in[4];
    const float* Wv = (const float*)d_in[5];
    const float* bv = (const float*)d_in[6];
    const float* Wo = (const float*)d_in[7];
    float* out = (float*)d_out;

    // idempotent, called every launch (no static guards allowed)
    cudaFuncSetAttribute(attn_kernel,
                         cudaFuncAttributeMaxDynamicSharedMemorySize, ATT_SMEM);

    qkv_kernel<<<dim3(NQKV/128, MM/128), 256>>>(x, Wq, bq, Wk, bk, Wv, bv);
    attn_kernel<<<dim3(SS/64, BB*HH), 256, ATT_SMEM>>>();
    oproj_kernel<<<dim3(EE/128, MM/128), 256>>>(Wo, out);
}

// round 15
// speedup vs baseline: 1.0002x; 1.0002x over previous
#include <cuda_runtime.h>
#include <math.h>

#define BB   2
#define SS   2048
#define EE   2048
#define HH   16
#define KVH  4
#define DD   128
#define MM   (BB*SS)            // 4096
#define NQKV 3072
#define ATTN_SCALE 0.08838834764831845f   // 1/sqrt(128)

// ---------------- scratch (static device globals: allowed) ----------------
__device__ float g_q [(size_t)BB*HH *SS*DD];   // [B,H, S,D]  33.5 MB
__device__ float g_k [(size_t)BB*KVH*SS*DD];   // [B,KV,S,D]   8.4 MB
__device__ float g_v [(size_t)BB*KVH*SS*DD];   // [B,KV,S,D]   8.4 MB
__device__ float g_ao[(size_t)MM*EE];          // [B*S, H*D]  33.5 MB

// ============================================================================
// Kernel 1: fused QKV projection + bias + RoPE.
// C[m,n] = sum_k x[m,k]*W[n,k] + b[n]   for n in [0,3072)
//   n <  2048          -> Q (rope), head h = n>>7
//   2048 <= n < 2560   -> K (rope), kv head = (n-2048)>>7
//   n >= 2560          -> V (no rope)
// 128x128x16 SGEMM tile, 256 threads, 8x8 per-thread fragment. The N-tile is
// head-aligned, so fragment column groups (4tx+j) and (64+4tx+j) are exactly
// the RoPE pair (d, d+64) with d < 64.
// ============================================================================
__global__ __launch_bounds__(256) void qkv_kernel(
    const float* __restrict__ x,
    const float* __restrict__ Wq, const float* __restrict__ bq,
    const float* __restrict__ Wk, const float* __restrict__ bk,
    const float* __restrict__ Wv, const float* __restrict__ bv)
{
    __shared__ float As[16][132];
    __shared__ float Bs[16][132];

    const int tid = threadIdx.x;
    const int tx  = tid & 15;
    const int ty  = tid >> 4;
    const int m0  = blockIdx.y * 128;
    const int n0  = blockIdx.x * 128;

    const int lrow = tid >> 2;          // 0..63
    const int kq   = (tid & 3) << 2;    // 0,4,8,12

    // region selection (uniform per CTA: N-tile never crosses a region)
    int nbase; const float* W; const float* bvec;
    if (n0 < 2048)      { nbase = 0;    W = Wq; bvec = bq; }
    else if (n0 < 2560) { nbase = 2048; W = Wk; bvec = bk; }
    else                { nbase = 2560; W = Wv; bvec = bv; }

    const float* ap0 = x + (size_t)(m0 + lrow) * EE + kq;
    const float* ap1 = ap0 + (size_t)64 * EE;
    const float* bp0 = W + (size_t)(n0 - nbase + lrow) * EE + kq;
    const float* bp1 = bp0 + (size_t)64 * EE;

    float acc[8][8];
#pragma unroll
    for (int i = 0; i < 8; i++)
#pragma unroll
        for (int j = 0; j < 8; j++) acc[i][j] = 0.f;

    for (int k0 = 0; k0 < EE; k0 += 16) {
        float4 a0 = *(const float4*)(ap0 + k0);
        float4 a1 = *(const float4*)(ap1 + k0);
        float4 b0 = *(const float4*)(bp0 + k0);
        float4 b1 = *(const float4*)(bp1 + k0);
        __syncthreads();
        As[kq+0][lrow]    = a0.x; As[kq+1][lrow]    = a0.y;
        As[kq+2][lrow]    = a0.z; As[kq+3][lrow]    = a0.w;
        As[kq+0][lrow+64] = a1.x; As[kq+1][lrow+64] = a1.y;
        As[kq+2][lrow+64] = a1.z; As[kq+3][lrow+64] = a1.w;
        Bs[kq+0][lrow]    = b0.x; Bs[kq+1][lrow]    = b0.y;
        Bs[kq+2][lrow]    = b0.z; Bs[kq+3][lrow]    = b0.w;
        Bs[kq+0][lrow+64] = b1.x; Bs[kq+1][lrow+64] = b1.y;
        Bs[kq+2][lrow+64] = b1.z; Bs[kq+3][lrow+64] = b1.w;
        __syncthreads();
#pragma unroll
        for (int kk = 0; kk < 16; kk++) {
            float4 A0 = *(const float4*)&As[kk][4*ty];
            float4 A1 = *(const float4*)&As[kk][64 + 4*ty];
            float4 B0 = *(const float4*)&Bs[kk][4*tx];
            float4 B1 = *(const float4*)&Bs[kk][64 + 4*tx];
            float ar[8] = {A0.x,A0.y,A0.z,A0.w,A1.x,A1.y,A1.z,A1.w};
            float br[8] = {B0.x,B0.y,B0.z,B0.w,B1.x,B1.y,B1.z,B1.w};
#pragma unroll
            for (int i = 0; i < 8; i++)
#pragma unroll
                for (int j = 0; j < 8; j++)
                    acc[i][j] = fmaf(ar[i], br[j], acc[i][j]);
        }
    }

    // ---------------- epilogue: bias + RoPE + scatter ----------------
    const int bi  = m0 >> 11;              // batch (m tile never crosses batch)
    const int si0 = (m0 & (SS - 1)) + 4*ty;

    float bias0[4], bias1[4];
#pragma unroll
    for (int j = 0; j < 4; j++) {
        bias0[j] = bvec[n0 - nbase + 4*tx + j];
        bias1[j] = bvec[n0 - nbase + 64 + 4*tx + j];
    }

    float* dst; bool rope;
    if (n0 < 2048) {
        int h = n0 >> 7;
        dst = g_q + (((size_t)bi*HH + h) * SS) * DD;  rope = true;
    } else if (n0 < 2560) {
        int kv = (n0 - 2048) >> 7;
        dst = g_k + (((size_t)bi*KVH + kv) * SS) * DD; rope = true;
    } else {
        int kv = (n0 - 2560) >> 7;
        dst = g_v + (((size_t)bi*KVH + kv) * SS) * DD; rope = false;
    }

    float invf[4];
#pragma unroll
    for (int j = 0; j < 4; j++)
        invf[j] = powf(10000.0f, -(float)(4*tx + j) * (1.0f / 64.0f));

#pragma unroll
    for (int i = 0; i < 8; i++) {
        int s = si0 + ((i < 4) ? i : (60 + i));   // rows 4ty+i and 64+4ty+(i-4)
        float out0[4], out1[4];
#pragma unroll
        for (int j = 0; j < 4; j++) {
            float v0 = acc[i][j]     + bias0[j];
            float v1 = acc[i][4 + j] + bias1[j];
            if (rope) {
                float sn, cs;
                sincosf((float)s * invf[j], &sn, &cs);
                out0[j] = v0 * cs - v1 * sn;
                out1[j] = v1 * cs + v0 * sn;
            } else {
                out0[j] = v0;
                out1[j] = v1;
            }
        }
        float* row = dst + (size_t)s * DD;
        *(float4*)(row + 4*tx)      = make_float4(out0[0], out0[1], out0[2], out0[3]);
        *(float4*)(row + 64 + 4*tx) = make_float4(out1[0], out1[1], out1[2], out1[3]);
    }
}

// ============================================================================
// Kernel 2: causal flash attention, fp32, 64x64 tiles, online softmax.
// grid = (32 q-tiles [reversed: biggest first], 32 = B*H); 256 threads.
// Fragment mapping: thread(ty,tx) owns score rows {ty+16w}, cols {tx+16u};
// O rows {ty+16w}, cols {4tx+j, 64+4tx+j}. Row statistics reduce across the
// 16 lanes sharing ty via shfl.xor (width-16 groups inside each warp).
// ============================================================================
#define ATT_SMEM ((3*64*132 + 64*68) * 4)   // 118784 B

__global__ __launch_bounds__(256) void attn_kernel()
{
    extern __shared__ float sm[];
    float* Qs = sm;                    // [64][132]  (row m, d)
    float* Ks = sm + 64*132;           // [64][132]  (row n, d)
    float* Vs = sm + 2*64*132;         // [64][132]  (row n, d)
    float* Ps = sm + 3*64*132;         // [64][68]   (row m, n)

    const int tid = threadIdx.x;
    const int tx  = tid & 15;
    const int ty  = tid >> 4;
    const int qt  = (int)(gridDim.x - 1) - (int)blockIdx.x;  // big tiles first
    const int bh  = blockIdx.y;
    const int b   = bh >> 4;
    const int h   = bh & 15;
    const int kvh = h >> 2;            // G = 4
    const int q0  = qt * 64;

    const float* qbase = g_q + (((size_t)b*HH  + h  ) * SS + q0) * DD;
    const float* kbase = g_k + (((size_t)b*KVH + kvh) * SS) * DD;
    const float* vbase = g_v + (((size_t)b*KVH + kvh) * SS) * DD;

    // load Q tile once
#pragma unroll
    for (int i = 0; i < 8; i++) {
        int f  = tid + 256*i;
        int r  = f >> 5;
        int d4 = (f & 31) << 2;
        *(float4*)&Qs[r*132 + d4] = *(const float4*)(qbase + (size_t)r*DD + d4);
    }

    float o[4][8];
    float mi[4], li[4];
#pragma unroll
    for (int w = 0; w < 4; w++) {
        mi[w] = -1e30f; li[w] = 0.f;
#pragma unroll
        for (int j = 0; j < 8; j++) o[w][j] = 0.f;
    }

    const int nk = qt + 1;
    for (int kt = 0; kt < nk; kt++) {
        const float* kp = kbase + (size_t)kt * 64 * DD;
        const float* vp = vbase + (size_t)kt * 64 * DD;

        __syncthreads();   // previous iteration finished reading Ks/Vs/Ps
#pragma unroll
        for (int i = 0; i < 8; i++) {
            int f  = tid + 256*i;
            int r  = f >> 5;
            int d4 = (f & 31) << 2;
            *(float4*)&Ks[r*132 + d4] = *(const float4*)(kp + (size_t)r*DD + d4);
            *(float4*)&Vs[r*132 + d4] = *(const float4*)(vp + (size_t)r*DD + d4);
        }
        __syncthreads();

        // ---- scores S = Q K^T ----
        float sc[4][4];
#pragma unroll
        for (int w = 0; w < 4; w++)
#pragma unroll
            for (int u = 0; u < 4; u++) sc[w][u] = 0.f;

#pragma unroll 4
        for (int k = 0; k < DD; k += 4) {
            float4 qv[4], kv[4];
#pragma unroll
            for (int w = 0; w < 4; w++) qv[w] = *(const float4*)&Qs[(ty + 16*w)*132 + k];
#pragma unroll
            for (int u = 0; u < 4; u++) kv[u] = *(const float4*)&Ks[(tx + 16*u)*132 + k];
#pragma unroll
            for (int w = 0; w < 4; w++)
#pragma unroll
                for (int u = 0; u < 4; u++) {
                    sc[w][u] = fmaf(qv[w].x, kv[u].x, sc[w][u]);
                    sc[w][u] = fmaf(qv[w].y, kv[u].y, sc[w][u]);
                    sc[w][u] = fmaf(qv[w].z, kv[u].z, sc[w][u]);
                    sc[w][u] = fmaf(qv[w].w, kv[u].w, sc[w][u]);
                }
        }

        // ---- scale, causal mask, online softmax ----
        const bool diag = (kt == qt);
        float alpha[4];
#pragma unroll
        for (int w = 0; w < 4; w++) {
            const int r = ty + 16*w;
            float rowm = -1e30f;
#pragma unroll
            for (int u = 0; u < 4; u++) {
                float s = sc[w][u] * ATTN_SCALE;
                if (diag && (tx + 16*u > r)) s = -1e30f;
                sc[w][u] = s;
                rowm = fmaxf(rowm, s);
            }
#pragma unroll
            for (int off = 8; off >= 1; off >>= 1)
                rowm = fmaxf(rowm, __shfl_xor_sync(0xffffffffu, rowm, off));
            float mnew = fmaxf(mi[w], rowm);
            alpha[w] = __expf(mi[w] - mnew);
            float rs = 0.f;
#pragma unroll
            for (int u = 0; u < 4; u++) {
                float p = __expf(sc[w][u] - mnew);
                Ps[r*68 + tx + 16*u] = p;
                rs += p;
            }
#pragma unroll
            for (int off = 8; off >= 1; off >>= 1)
                rs += __shfl_xor_sync(0xffffffffu, rs, off);
            li[w] = li[w] * alpha[w] + rs;
            mi[w] = mnew;
        }
        __syncthreads();   // Ps visible to all

        // ---- rescale O and accumulate O += P V ----
#pragma unroll
        for (int w = 0; w < 4; w++)
#pragma unroll
            for (int j = 0; j < 8; j++) o[w][j] *= alpha[w];

#pragma unroll 4
        for (int n = 0; n < 64; n += 4) {
            float pr[4][4];
#pragma unroll
            for (int w = 0; w < 4; w++) {
                float4 t = *(const float4*)&Ps[(ty + 16*w)*68 + n];
                pr[w][0] = t.x; pr[w][1] = t.y; pr[w][2] = t.z; pr[w][3] = t.w;
            }
#pragma unroll
            for (int nn = 0; nn < 4; nn++) {
                float4 v0 = *(const float4*)&Vs[(n + nn)*132 + 4*tx];
                float4 v1 = *(const float4*)&Vs[(n + nn)*132 + 64 + 4*tx];
#pragma unroll
                for (int w = 0; w < 4; w++) {
                    float p = pr[w][nn];
                    o[w][0] = fmaf(p, v0.x, o[w][0]);
                    o[w][1] = fmaf(p, v0.y, o[w][1]);
                    o[w][2] = fmaf(p, v0.z, o[w][2]);
                    o[w][3] = fmaf(p, v0.w, o[w][3]);
                    o[w][4] = fmaf(p, v1.x, o[w][4]);
                    o[w][5] = fmaf(p, v1.y, o[w][5]);
                    o[w][6] = fmaf(p, v1.z, o[w][6]);
                    o[w][7] = fmaf(p, v1.w, o[w][7]);
                }
            }
        }
    }

    // ---- normalize and write to g_ao [B*S, H*D] ----
#pragma unroll
    for (int w = 0; w < 4; w++) {
        const int r = ty + 16*w;
        const int s = q0 + r;
        const float inv = 1.0f / li[w];
        float* dst = g_ao + ((size_t)b*SS + s) * EE + h*DD + 4*tx;
        *(float4*)dst =
            make_float4(o[w][0]*inv, o[w][1]*inv, o[w][2]*inv, o[w][3]*inv);
        *(float4*)(dst + 64) =
            make_float4(o[w][4]*inv, o[w][5]*inv, o[w][6]*inv, o[w][7]*inv);
    }
}

// ============================================================================
// Kernel 3: output projection. out[m,e] = sum_hd ao[m,hd] * Wo[e,hd]
// Same 128x128x16 SGEMM skeleton, no bias, direct to d_out.
// ============================================================================
__global__ __launch_bounds__(256) void oproj_kernel(
    const float* __restrict__ Wo, float* __restrict__ out)
{
    __shared__ float As[16][132];
    __shared__ float Bs[16][132];

    const int tid = threadIdx.x;
    const int tx  = tid & 15;
    const int ty  = tid >> 4;
    const int m0  = blockIdx.y * 128;
    const int n0  = blockIdx.x * 128;

    const int lrow = tid >> 2;
    const int kq   = (tid & 3) << 2;

    const float* ap0 = g_ao + (size_t)(m0 + lrow) * EE + kq;
    const float* ap1 = ap0 + (size_t)64 * EE;
    const float* bp0 = Wo + (size_t)(n0 + lrow) * EE + kq;
    const float* bp1 = bp0 + (size_t)64 * EE;

    float acc[8][8];
#pragma unroll
    for (int i = 0; i < 8; i++)
#pragma unroll
        for (int j = 0; j < 8; j++) acc[i][j] = 0.f;

    for (int k0 = 0; k0 < EE; k0 += 16) {
        float4 a0 = *(const float4*)(ap0 + k0);
        float4 a1 = *(const float4*)(ap1 + k0);
        float4 b0 = *(const float4*)(bp0 + k0);
        float4 b1 = *(const float4*)(bp1 + k0);
        __syncthreads();
        As[kq+0][lrow]    = a0.x; As[kq+1][lrow]    = a0.y;
        As[kq+2][lrow]    = a0.z; As[kq+3][lrow]    = a0.w;
        As[kq+0][lrow+64] = a1.x; As[kq+1][lrow+64] = a1.y;
        As[kq+2][lrow+64] = a1.z; As[kq+3][lrow+64] = a1.w;
        Bs[kq+0][lrow]    = b0.x; Bs[kq+1][lrow]    = b0.y;
        Bs[kq+2][lrow]    = b0.z; Bs[kq+3][lrow]    = b0.w;
        Bs[kq+0][lrow+64] = b1.x; Bs[kq+1][lrow+64] = b1.y;
        Bs[kq+2][lrow+64] = b1.z; Bs[kq+3][lrow+64] = b1.w;
        __syncthreads();
#pragma unroll
        for (int kk = 0; kk < 16; kk++) {
            float4 A0 = *(const float4*)&As[kk][4*ty];
            float4 A1 = *(const float4*)&As[kk][64 + 4*ty];
            float4 B0 = *(const float4*)&Bs[kk][4*tx];
            float4 B1 = *(const float4*)&Bs[kk][64 + 4*tx];
            float ar[8] = {A0.x,A0.y,A0.z,A0.w,A1.x,A1.y,A1.z,A1.w};
            float br[8] = {B0.x,B0.y,B0.z,B0.w,B1.x,B1.y,B1.z,B1.w};
#pragma unroll
            for (int i = 0; i < 8; i++)
#pragma unroll
                for (int j = 0; j < 8; j++)
                    acc[i][j] = fmaf(ar[i], br[j], acc[i][j]);
        }
    }

#pragma unroll
    for (int i = 0; i < 8; i++) {
        int m = m0 + 4*ty + ((i < 4) ? i : (60 + i));
        float* row = out + (size_t)m * EE + n0;
        *(float4*)(row + 4*tx) =
            make_float4(acc[i][0], acc[i][1], acc[i][2], acc[i][3]);
        *(float4*)(row + 64 + 4*tx) =
            make_float4(acc[i][4], acc[i][5], acc[i][6], acc[i][7]);
    }
}

// ============================================================================
extern "C" void kernel_launch(void* const* d_in, const int* in_sizes, int n_in,
                              void* d_out, int out_size)
{
    (void)in_sizes; (void)n_in; (void)out_size;
    const float* x  = (const float*)d_in[0];
    const float* Wq = (const float*)d_in[1];
    const float* bq = (const float*)d_in[2];
    const float* Wk = (const float*)d_in[3];
    const float* bk = (const float*)d_in[4];
    const float* Wv = (const float*)d_in[5];
    const float* bv = (const float*)d_in[6];
    const float* Wo = (const float*)d_in[7];
    float* out = (float*)d_out;

    // idempotent, called every launch (no static guards allowed)
    cudaFuncSetAttribute(attn_kernel,
                         cudaFuncAttributeMaxDynamicSharedMemorySize, ATT_SMEM);

    qkv_kernel<<<dim3(NQKV/128, MM/128), 256>>>(x, Wq, bq, Wk, bk, Wv, bv);
    attn_kernel<<<dim3(SS/64, BB*HH), 256, ATT_SMEM>>>();
    oproj_kernel<<<dim3(EE/128, MM/128), 256>>>(Wo, out);
}